// round 16
// baseline (speedup 1.0000x reference)
#include <cuda_runtime.h>

#define BB 4
#define EE 1500
#define DD 256
#define HH 8
#define DK 32

#define O_ATTN 1536000
#define O_APE  73536000
#define D8_LD 1504

typedef unsigned long long ull;

// ---------------- scratch (no allocation allowed) ----------------
__device__ float g_q[BB*HH*EE*DK];            // scaled q, [b,h,e,dk]
__device__ ulonglong2 g_k2[BB*HH*12*1024];    // K pair-transposed, chunk-major: [bh][c][j][64]
__device__ float g_v[BB*HH*1536*DK];          // V natural [k][d], padded to 1536 rows
__device__ float g_qdr[BB*HH*EE*8];           // q . base_rpr[p], p padded to 8
__device__ float g_o[BB*EE*DD];               // attention output pre-FC, [b,e,h*32+d]
__device__ float g_asum[BB*EE];
__device__ int   g_acnt[BB*EE];
__device__ unsigned char g_d8[BB*EE*D8_LD];   // dist compressed: 0..3 valid, 255 masked

__device__ __forceinline__ float warp_sum(float v) {
    #pragma unroll
    for (int o = 16; o; o >>= 1) v += __shfl_xor_sync(0xffffffffu, v, o);
    return v;
}

// packed f32x2 helpers (sm_100+)
__device__ __forceinline__ void fma2(ull &d, ull a, ull b) {
    asm("fma.rn.f32x2 %0, %1, %2, %0;" : "+l"(d) : "l"(a), "l"(b));
}
__device__ __forceinline__ ull f2add(ull a, ull b) {
    ull d;
    asm("add.rn.f32x2 %0, %1, %2;" : "=l"(d) : "l"(a), "l"(b));
    return d;
}
__device__ __forceinline__ ull f2mul(ull a, ull b) {
    ull d;
    asm("mul.rn.f32x2 %0, %1, %2;" : "=l"(d) : "l"(a), "l"(b));
    return d;
}
__device__ __forceinline__ float f2sum(ull u) {
    float lo, hi;
    asm("mov.b64 {%0,%1}, %2;" : "=f"(lo), "=f"(hi) : "l"(u));
    return lo + hi;
}
__device__ __forceinline__ ull packf2(float x, float y) {
    ull u;
    asm("mov.b64 %0, {%1,%2};" : "=l"(u) : "f"(x), "f"(y));
    return u;
}
__device__ __forceinline__ ull shfl_xor_ull(ull v, int m) {
    unsigned lo = (unsigned)v, hi = (unsigned)(v >> 32);
    lo = __shfl_xor_sync(0xffffffffu, lo, m);
    hi = __shfl_xor_sync(0xffffffffu, hi, m);
    return ((ull)hi << 32) | lo;
}

// ---------------- mbarrier + bulk-copy helpers ----------------
__device__ __forceinline__ void mbar_init(unsigned a, unsigned cnt) {
    asm volatile("mbarrier.init.shared.b64 [%0], %1;" :: "r"(a), "r"(cnt) : "memory");
}
__device__ __forceinline__ void mbar_expect_tx(unsigned a, unsigned bytes) {
    asm volatile("mbarrier.arrive.expect_tx.shared.b64 _, [%0], %1;"
                 :: "r"(a), "r"(bytes) : "memory");
}
__device__ __forceinline__ void bulk_g2s(unsigned dst, const void* src, unsigned bytes, unsigned mbar) {
    asm volatile("cp.async.bulk.shared::cta.global.mbarrier::complete_tx::bytes [%0], [%1], %2, [%3];"
                 :: "r"(dst), "l"(src), "r"(bytes), "r"(mbar) : "memory");
}
#define MBAR_WAIT(addr, par) do { \
    asm volatile( \
        "{\n\t.reg .pred P;\n\t" \
        "WL%=:\n\t" \
        "mbarrier.try_wait.parity.acquire.cta.shared::cta.b64 P, [%0], %1, 0x989680;\n\t" \
        "@P bra WD%=;\n\t" \
        "bra WL%=;\n\t" \
        "WD%=:\n\t}" \
        :: "r"(addr), "r"(par) : "memory"); \
} while (0)

#define GROUP_BAR(gid) \
    asm volatile("bar.sync %0, 256;" :: "r"((gid) + 1) : "memory")

// ---------------- K0: zero accumulators ----------------
__global__ void zero_kernel() {
    int i = blockIdx.x * 256 + threadIdx.x;
    if (i < BB*EE) { g_asum[i] = 0.f; g_acnt[i] = 0; }
}

// ---------------- K0b: valid counts + d8 compression ----------------
__global__ void __launch_bounds__(256) countwrite_kernel(const int* __restrict__ dist) {
    int b  = blockIdx.y;
    int q0 = blockIdx.x * 8;
    int t  = threadIdx.x;
    const int* dpb = dist + (long long)b*EE*EE;
    unsigned char* d8 = g_d8 + (long long)b*EE*D8_LD;
    for (int k = t; k < EE; k += 256) {
        int cnt = 0;
        #pragma unroll
        for (int r = 0; r < 8; r++) {
            int q = q0 + r;
            if (q < EE) {
                int dv = dpb[(long long)q*EE + k];
                bool ok = (dv <= 3);
                d8[q*D8_LD + k] = ok ? (unsigned char)dv : (unsigned char)255;
                cnt += ok ? 1 : 0;
            }
        }
        atomicAdd(&g_acnt[b*EE + k], cnt);
    }
}

// ---------------- K1: layernorm + QKV projections (16 rows, 512 threads) ----------------
__global__ void __launch_bounds__(512) proj_kernel(
    const float* __restrict__ x,
    const float* __restrict__ Wq, const float* __restrict__ Wk,
    const float* __restrict__ Wv,
    const float* __restrict__ lnw, const float* __restrict__ lnb,
    const float* __restrict__ rpr)
{
    __shared__ __align__(16) float ssm[256*16];   // [d][r16] raw input; later K transpose buf
    __shared__ __align__(16) float nsm[256*16];   // [d][r16] layernormed
    int b  = blockIdx.y;
    int e0 = blockIdx.x * 16;
    int t  = threadIdx.x;
    const float* xb = x + b*(DD*EE);

    for (int i = t; i < 4096; i += 512) {
        int d = i >> 4, r = i & 15;
        int e = e0 + r;
        ssm[i] = (e < EE) ? xb[d*EE + e] : 0.f;
    }
    __syncthreads();

    int w = t >> 5, lane = t & 31;
    {   // layernorm of row w (one row per warp, 16 warps, 16 rows)
        float s = 0.f;
        #pragma unroll
        for (int i = 0; i < 8; i++) s += ssm[(lane + 32*i)*16 + w];
        s = warp_sum(s);
        float mu = s * (1.f/256.f);
        float vs = 0.f;
        #pragma unroll
        for (int i = 0; i < 8; i++) {
            float dlt = ssm[(lane + 32*i)*16 + w] - mu;
            vs += dlt*dlt;
        }
        vs = warp_sum(vs);
        float rstd = rsqrtf(vs * (1.f/256.f) + 1e-6f);
        #pragma unroll
        for (int i = 0; i < 8; i++) {
            int d = lane + 32*i;
            nsm[d*16 + w] = (ssm[d*16 + w] - mu) * rstd * lnw[d] + lnb[d];
        }
    }
    __syncthreads();

    // thread = (j = t&255 output column, rh = t>>8 row half)
    int j  = t & 255;
    int rh = t >> 8;
    int rb = rh * 8;            // first local row of this thread's half

    float aq[8], ak[8], av[8];
    #pragma unroll
    for (int r = 0; r < 8; r++) { aq[r] = 0.f; ak[r] = 0.f; av[r] = 0.f; }

    #pragma unroll 4
    for (int d = 0; d < 256; d++) {
        float wq = Wq[d*256 + j];
        float wk = Wk[d*256 + j];
        float wv = Wv[d*256 + j];
        float4 s0 = *(const float4*)&ssm[d*16 + rb];
        float4 s1 = *(const float4*)&ssm[d*16 + rb + 4];
        float4 n0 = *(const float4*)&nsm[d*16 + rb];
        float4 n1 = *(const float4*)&nsm[d*16 + rb + 4];
        aq[0] += n0.x*wq; aq[1] += n0.y*wq; aq[2] += n0.z*wq; aq[3] += n0.w*wq;
        aq[4] += n1.x*wq; aq[5] += n1.y*wq; aq[6] += n1.z*wq; aq[7] += n1.w*wq;
        ak[0] += s0.x*wk; ak[1] += s0.y*wk; ak[2] += s0.z*wk; ak[3] += s0.w*wk;
        ak[4] += s1.x*wk; ak[5] += s1.y*wk; ak[6] += s1.z*wk; ak[7] += s1.w*wk;
        av[0] += s0.x*wv; av[1] += s0.y*wv; av[2] += s0.z*wv; av[3] += s0.w*wv;
        av[4] += s1.x*wv; av[5] += s1.y*wv; av[6] += s1.z*wv; av[7] += s1.w*wv;
    }

    int h = (j >> 5), dk = j & 31;
    int bh = b*HH + h;
    const float inv_sqrt_dk = 0.17677669529663687f;  // 1/sqrt(32)
    float qsv[8];
    #pragma unroll
    for (int r = 0; r < 8; r++) qsv[r] = aq[r] * inv_sqrt_dk;

    #pragma unroll
    for (int r = 0; r < 8; r++) {
        int e = e0 + rb + r;
        if (e < EE) {
            g_q[(bh*EE + e)*32 + dk] = qsv[r];
            g_v[((long long)bh*1536 + e)*32 + dk] = av[r];
        }
    }

    // qdr: warp = (h = w&7, rh = w>>3), lane = dk
    #pragma unroll
    for (int p = 0; p < 6; p++) {
        float rv = rpr[p*32 + lane];
        #pragma unroll
        for (int r = 0; r < 8; r++) {
            float pv = warp_sum(qsv[r] * rv);
            int e = e0 + rb + r;
            if (lane == 0 && e < EE)
                g_qdr[(bh*EE + e)*8 + p] = pv;
        }
    }

    // ---- K pair-transpose into chunk-major g_k2[bh][c][j16][64] ----
    __syncthreads();                       // all ssm/nsm reads done
    #pragma unroll
    for (int r = 0; r < 8; r++) ssm[j*16 + rb + r] = ak[r];   // ssm[(h*32+dk)*16 + row]
    __syncthreads();
    {
        int hh = t >> 6;                   // 0..7
        int jj = (t >> 2) & 15;            // 0..15 d-pair
        int ph = t & 3;                    // covers 2 of the 8 local pairs
        const float* s0 = &ssm[(hh*32 + 2*jj    )*16];
        const float* s1 = &ssm[(hh*32 + 2*jj + 1)*16];
        int pg = e0 >> 1;                  // first pair (multiple of 8)
        int cc = pg >> 6, pl = pg & 63;
        long long base = (((long long)(b*HH + hh)*12 + cc)*16 + jj)*64 + pl + 2*ph;
        #pragma unroll
        for (int ps = 0; ps < 2; ps++) {
            int pr = 2*(2*ph + ps);        // local even row of this pair
            ulonglong2 val;
            val.x = packf2(s0[pr],     s1[pr]);
            val.y = packf2(s0[pr + 1], s1[pr + 1]);
            g_k2[base + ps] = val;
        }
    }
}

// ---------------- K2: attention (two independent 256-thread groups) ----------------
#define SC_LD 1512
// floats: mbar 16 + sc 16*1512 + 4 bufs (4*4096) + qsm 512 + qdr 128 + flaginv 16 + invr 16
#define SMEM_ATTN ((16 + 16*SC_LD + 4*4096 + 512 + 128 + 16 + 16)*4)
#define CHUNK_BYTES 16384u

__global__ void __launch_bounds__(512, 1) attn_kernel(float* __restrict__ out)
{
    extern __shared__ __align__(16) float sm[];
    float* sc      = sm + 16;                // 16 x 1512 (group g owns rows [8g, 8g+8))
    float* bufs    = sc + 16*SC_LD;          // 4 x 4096 floats: [g][buf]
    float* qsm     = bufs + 4*4096;          // 16 x 32 scaled q
    float* qdr     = qsm + 512;              // 16 x 8 bias table
    float* flaginv = qdr + 128;              // 16: inv (or 0 if fullmask)
    float* invr    = flaginv + 16;           // 16: inv always

    int qt = blockIdx.x, h = blockIdx.y, b = blockIdx.z;
    int q0 = qt * 16;
    int t  = threadIdx.x;
    int g  = t >> 8;          // group 0/1
    int gt = t & 255;         // thread within group
    int w8 = gt >> 5;         // warp within group
    int lane = gt & 31;
    int bh = b*HH + h;

    // per-group views
    float* scg      = sc + g*8*SC_LD;
    float* buf0f    = bufs + g*2*4096;
    float* buf1f    = buf0f + 4096;
    float* qsmg     = qsm + g*256;
    float* qdrg     = qdr + g*64;
    float* flaginvg = flaginv + g*8;
    float* invrg    = invr + g*8;

    unsigned smb = (unsigned)__cvta_generic_to_shared(sm) + g*32;
    unsigned mbK0 = smb, mbK1 = smb + 8, mbV0 = smb + 16, mbV1 = smb + 24;
    unsigned bsm0 = (unsigned)__cvta_generic_to_shared(buf0f);
    unsigned bsm1 = (unsigned)__cvta_generic_to_shared(buf1f);

    const ulonglong2* k2base = g_k2 + (long long)bh*12*1024;
    const float* vbase = g_v + (long long)bh*1536*32;
    const unsigned char* d8b = g_d8 + (long long)b*EE*D8_LD;

    // prologue: q rows for this group (8 rows x 32), bias rows, mbar init, first K copies
    {
        int qg = q0 + g*8 + (gt >> 5);
        qsmg[gt] = (qg < EE) ? g_q[(bh*EE + qg)*32 + (gt & 31)] : 0.f;
    }
    if (gt < 64) {
        int qg = q0 + g*8 + (gt >> 3);
        qdrg[gt] = (qg < EE) ? g_qdr[(bh*EE + qg)*8 + (gt & 7)] : 0.f;
    }
    if (gt == 0) {
        mbar_init(mbK0, 1); mbar_init(mbK1, 1);
        mbar_init(mbV0, 1); mbar_init(mbV1, 1);
        mbar_expect_tx(mbK0, CHUNK_BYTES);
        bulk_g2s(bsm0, k2base, CHUNK_BYTES, mbK0);
        mbar_expect_tx(mbK1, CHUNK_BYTES);
        bulk_g2s(bsm1, k2base + 1024, CHUNK_BYTES, mbK1);
    }
    GROUP_BAR(g);

    // ================= score phase =================
    // group warp w8 owns pairs [w8*8, w8*8+8); lane: qq = (gt>>3)&3, kl = gt&7
    int qq = (gt >> 3) & 3;
    int p0i = w8*8 + (gt & 7);
    int qg0 = q0 + g*8 + qq, qg1 = qg0 + 4;

    // Q rows into registers (broadcast LDS, once)
    ull qr0[16], qr1[16];
    {
        const ull* a = (const ull*)(qsmg + qq*32);
        const ull* bq = (const ull*)(qsmg + (qq + 4)*32);
        #pragma unroll
        for (int jj = 0; jj < 16; jj++) { qr0[jj] = a[jj]; qr1[jj] = bq[jj]; }
    }

    // d8 prologue for chunk 0
    uchar2 dA, dB;
    {
        int kgA = 2*p0i;
        dA = (qg0 < EE) ? *(const uchar2*)(d8b + (long long)qg0*D8_LD + kgA) : make_uchar2(255, 255);
        dB = (qg1 < EE) ? *(const uchar2*)(d8b + (long long)qg1*D8_LD + kgA) : make_uchar2(255, 255);
    }

    for (int c = 0; c < 12; c++) {
        int kc = c * 128;
        // prefetch d8 for chunk c+1 (overlaps mbar wait + compute)
        uchar2 eA = make_uchar2(255, 255), eB = make_uchar2(255, 255);
        if (c < 11) {
            int kg2 = kc + 128 + 2*p0i;
            if (kg2 < EE) {
                if (qg0 < EE) eA = *(const uchar2*)(d8b + (long long)qg0*D8_LD + kg2);
                if (qg1 < EE) eB = *(const uchar2*)(d8b + (long long)qg1*D8_LD + kg2);
            }
        }

        MBAR_WAIT((c & 1) ? mbK1 : mbK0, (c >> 1) & 1);

        const ulonglong2* bp = (const ulonglong2*)((c & 1) ? buf1f : buf0f);
        const ulonglong2* prow = bp + p0i;
        ull a00 = 0, a01 = 0, a10 = 0, a11 = 0;
        #pragma unroll
        for (int jj = 0; jj < 16; jj++) {
            ulonglong2 kv = prow[jj*64];
            fma2(a00, qr0[jj], kv.x); fma2(a01, qr0[jj], kv.y);
            fma2(a10, qr1[jj], kv.x); fma2(a11, qr1[jj], kv.y);
        }

        // epilogue: bias + mask + paired store
        int kgA = kc + 2*p0i;
        if (kgA < EE) {
            float sa = -1e9f, sb = -1e9f;
            if (dA.x <= 3) sa = f2sum(a00) + qdrg[qq*8 + dA.x];
            if (dA.y <= 3) sb = f2sum(a01) + qdrg[qq*8 + dA.y];
            *(ull*)&scg[qq*SC_LD + kgA] = packf2(sa, sb);
            sa = -1e9f; sb = -1e9f;
            if (dB.x <= 3) sa = f2sum(a10) + qdrg[(qq + 4)*8 + dB.x];
            if (dB.y <= 3) sb = f2sum(a11) + qdrg[(qq + 4)*8 + dB.y];
            *(ull*)&scg[(qq + 4)*SC_LD + kgA] = packf2(sa, sb);
        }
        GROUP_BAR(g);   // all reads of buf[c&1] done, sc stores visible
        if (gt == 0 && c < 10) {
            unsigned mb = (c & 1) ? mbK1 : mbK0;
            mbar_expect_tx(mb, CHUNK_BYTES);
            bulk_g2s((c & 1) ? bsm1 : bsm0, k2base + (c + 2)*1024, CHUNK_BYTES, mb);
        }
        dA = eA; dB = eB;
    }

    // issue V chunks 0,1 (overlap with softmax)
    if (gt == 0) {
        mbar_expect_tx(mbV0, CHUNK_BYTES);
        bulk_g2s(bsm0, vbase, CHUNK_BYTES, mbV0);
        mbar_expect_tx(mbV1, CHUNK_BYTES);
        bulk_g2s(bsm1, vbase + 128*32, CHUNK_BYTES, mbV1);
    }

    // ===== softmax, 2-pass (no max subtraction; masked -1e9 underflows to 0) =====
    {
        int rr = w8;                  // one row per group warp
        int qg = q0 + g*8 + rr;
        if (qg < EE) {
            float* row = scg + rr*SC_LD;
            float sum = 0.f;
            for (int k = lane*4; k < EE; k += 128) {
                float4 v = *(float4*)&row[k];
                v.x = __expf(v.x); v.y = __expf(v.y);
                v.z = __expf(v.z); v.w = __expf(v.w);
                *(float4*)&row[k] = v;
                sum += (v.x + v.y) + (v.z + v.w);
            }
            sum = warp_sum(sum);
            bool fullmask = (sum == 0.f);
            if (fullmask) {   // reference: softmax of all -1e9 -> uniform
                for (int k = lane*4; k < EE; k += 128)
                    *(float4*)&row[k] = make_float4(1.f, 1.f, 1.f, 1.f);
                sum = (float)EE;
            }
            float inv = 1.f / sum;
            if (lane == 0) {
                invrg[rr] = inv;
                flaginvg[rr] = fullmask ? 0.f : inv;
            }
            long long obase = (long long)O_ATTN + (long long)(bh*EE + qg)*EE;
            for (int k = lane*4; k < EE; k += 128) {
                float4 v = *(const float4*)&row[k];
                v.x *= inv; v.y *= inv; v.z *= inv; v.w *= inv;
                *(float4*)&out[obase + k] = v;
            }
        } else {
            if (lane == 0) { invrg[rr] = 0.f; flaginvg[rr] = 0.f; }
        }
    }
    GROUP_BAR(g);

    // column sums over this group's 8 rows (unnormalized exp * flaginv)
    for (int k = gt; k < EE; k += 256) {
        float s = 0.f;
        #pragma unroll
        for (int r = 0; r < 8; r++) s += scg[r*SC_LD + k] * flaginvg[r];
        atomicAdd(&g_asum[b*EE + k], s);
    }

    // ================= AV =================
    // thread = (ks = gt>>3: 32 k-slices of 4, dp = gt&7: float4 of d)
    // owns ALL 8 group rows; accumulates across all 12 chunks in registers.
    int ks = gt >> 3;
    int dp = gt & 7;
    ull accL[8], accH[8];
    #pragma unroll
    for (int r = 0; r < 8; r++) { accL[r] = 0; accH[r] = 0; }

    for (int c = 0; c < 12; c++) {
        int kc = c * 128;
        MBAR_WAIT((c & 1) ? mbV1 : mbV0, (c >> 1) & 1);
        const float4* bp4 = (const float4*)((c & 1) ? buf1f : buf0f);

        int kg0 = kc + ks*4;
        if (kg0 < EE) {
            float4 a[8];
            #pragma unroll
            for (int r = 0; r < 8; r++)
                a[r] = *(const float4*)&scg[r*SC_LD + kg0];
            #pragma unroll
            for (int kk = 0; kk < 4; kk++) {
                float4 vv = bp4[(ks*4 + kk)*8 + dp];
                ull v0 = packf2(vv.x, vv.y), v1 = packf2(vv.z, vv.w);
                #pragma unroll
                for (int r = 0; r < 8; r++) {
                    float f = (kk==0) ? a[r].x : (kk==1) ? a[r].y : (kk==2) ? a[r].z : a[r].w;
                    ull s = packf2(f, f);
                    fma2(accL[r], s, v0);
                    fma2(accH[r], s, v1);
                }
            }
        }
        GROUP_BAR(g);   // all reads of buf[c&1] done
        if (gt == 0 && c < 10) {
            unsigned mb = (c & 1) ? mbV1 : mbV0;
            mbar_expect_tx(mb, CHUNK_BYTES);
            bulk_g2s((c & 1) ? bsm1 : bsm0, vbase + (long long)(c + 2)*128*32, CHUNK_BYTES, mb);
        }
    }

    // intra-warp reduction over the 4 k-slices in this warp (lane bits 3,4)
    #pragma unroll
    for (int r = 0; r < 8; r++) {
        accL[r] = f2add(accL[r], shfl_xor_ull(accL[r], 8));
        accL[r] = f2add(accL[r], shfl_xor_ull(accL[r], 16));
        accH[r] = f2add(accH[r], shfl_xor_ull(accH[r], 8));
        accH[r] = f2add(accH[r], shfl_xor_ull(accH[r], 16));
    }

    // cross-warp k-reduction via smem partials (group's sc region is free now)
    {
        ulonglong2* part = (ulonglong2*)scg;   // [w8][row][dp] : 8*8*8 ull2 = 8 KB
        if (lane < 8) {   // dp == lane for these lanes
            #pragma unroll
            for (int r = 0; r < 8; r++) {
                ulonglong2 v; v.x = accL[r]; v.y = accH[r];
                part[(w8*8 + r)*8 + dp] = v;
            }
        }
    }
    GROUP_BAR(g);
    if (gt < 64) {
        const ulonglong2* part = (const ulonglong2*)scg;
        int row = gt >> 3, dpp = gt & 7;
        ull sA = 0, sB = 0;
        #pragma unroll
        for (int ww = 0; ww < 8; ww++) {
            ulonglong2 v = part[(ww*8 + row)*8 + dpp];
            sA = f2add(sA, v.x);
            sB = f2add(sB, v.y);
        }
        int qg = q0 + g*8 + row;
        if (qg < EE) {
            float iv = invrg[row];
            ull ivp = packf2(iv, iv);
            ulonglong2 o;
            o.x = f2mul(sA, ivp);
            o.y = f2mul(sB, ivp);
            *(ulonglong2*)&g_o[(b*EE + qg)*DD + h*32 + 4*dpp] = o;
        }
    }
}

// ---------------- K3: FC + residual + transpose-out (16 rows, 512 threads) ----------------
__global__ void __launch_bounds__(512) fc_kernel(
    const float* __restrict__ x, const float* __restrict__ Wfc,
    float* __restrict__ out)
{
    __shared__ __align__(16) float osm[256*16];   // [d][r16]
    int b  = blockIdx.y;
    int e0 = blockIdx.x * 16;
    int t  = threadIdx.x;

    for (int i = t; i < 4096; i += 512) {
        int r = i >> 8, d = i & 255;
        int e = e0 + r;
        osm[d*16 + r] = (e < EE) ? g_o[(b*EE + e)*DD + d] : 0.f;
    }
    __syncthreads();

    int j  = t & 255;
    int rh = t >> 8;
    int rb = rh * 8;
    const float* xb = x + b*DD*EE + j*EE;
    float acc[8];
    #pragma unroll
    for (int r = 0; r < 8; r++) {
        int e = e0 + rb + r;
        acc[r] = (e < EE) ? xb[e] : 0.f;   // residual
    }
    #pragma unroll 4
    for (int d = 0; d < 256; d++) {
        float wv = Wfc[d*256 + j];
        float4 o0 = *(const float4*)&osm[d*16 + rb];
        float4 o1 = *(const float4*)&osm[d*16 + rb + 4];
        acc[0] += o0.x*wv; acc[1] += o0.y*wv; acc[2] += o0.z*wv; acc[3] += o0.w*wv;
        acc[4] += o1.x*wv; acc[5] += o1.y*wv; acc[6] += o1.z*wv; acc[7] += o1.w*wv;
    }
    float* ob = out + b*DD*EE + j*EE + e0 + rb;
    if (e0 + rb + 8 <= EE) {
        *(float4*)ob       = make_float4(acc[0], acc[1], acc[2], acc[3]);
        *(float4*)(ob + 4) = make_float4(acc[4], acc[5], acc[6], acc[7]);
    } else {
        for (int r = 0; r < 8; r++)
            if (e0 + rb + r < EE) ob[r] = acc[r];
    }
}

// ---------------- K4: attn_per_edge ----------------
__global__ void finalize_kernel(float* __restrict__ out) {
    int i = blockIdx.x * 256 + threadIdx.x;
    if (i < BB*EE) {
        out[O_APE + i] = g_asum[i] / (float)g_acnt[i];
    }
}

// ---------------- launch ----------------
extern "C" void kernel_launch(void* const* d_in, const int* in_sizes, int n_in,
                              void* d_out, int out_size)
{
    const float* x    = (const float*)d_in[0];
    const int*   dist = (const int*)  d_in[1];
    const float* Wq   = (const float*)d_in[2];
    const float* Wk   = (const float*)d_in[3];
    const float* Wv   = (const float*)d_in[4];
    const float* Wfc  = (const float*)d_in[5];
    const float* lnw  = (const float*)d_in[6];
    const float* lnb  = (const float*)d_in[7];
    const float* rpr  = (const float*)d_in[8];
    float* out = (float*)d_out;

    cudaFuncSetAttribute(attn_kernel,
        cudaFuncAttributeMaxDynamicSharedMemorySize, SMEM_ATTN);

    zero_kernel<<<24, 256>>>();

    dim3 gc(188, BB);
    countwrite_kernel<<<gc, 256>>>(dist);

    dim3 g1(94, BB);
    proj_kernel<<<g1, 512>>>(x, Wq, Wk, Wv, lnw, lnb, rpr);

    dim3 g2(94, HH, BB);
    attn_kernel<<<g2, 512, SMEM_ATTN>>>(out);

    dim3 g3(94, BB);
    fc_kernel<<<g3, 512>>>(x, Wfc, out);

    finalize_kernel<<<24, 256>>>(out);
}

// round 17
// speedup vs baseline: 1.1067x; 1.1067x over previous
#include <cuda_runtime.h>

#define BB 4
#define EE 1500
#define DD 256
#define HH 8
#define DK 32

#define O_ATTN 1536000
#define O_APE  73536000
#define D8_LD 1504

typedef unsigned long long ull;

// ---------------- scratch (no allocation allowed) ----------------
__device__ float g_q[BB*HH*EE*DK];            // scaled q, [b,h,e,dk]
__device__ ulonglong2 g_k2[BB*HH*12*1024];    // K pair-transposed, chunk-major: [bh][c][j][64]
__device__ float g_v[BB*HH*1536*DK];          // V natural [k][d], padded to 1536 rows
__device__ float g_qdr[BB*HH*EE*8];           // q . base_rpr[p], p padded to 8
__device__ float g_o[BB*EE*DD];               // attention output pre-FC, [b,e,h*32+d]
__device__ float g_asum[BB*EE];
__device__ int   g_acnt[BB*EE];
__device__ unsigned char g_d8[BB*EE*D8_LD];   // dist compressed: 0..3 valid, 255 masked
__device__ ull g_w2q[128*256];                // paired weights: {W[2j][col], W[2j+1][col]}
__device__ ull g_w2k[128*256];
__device__ ull g_w2v[128*256];
__device__ ull g_w2f[128*256];

__device__ __forceinline__ float warp_sum(float v) {
    #pragma unroll
    for (int o = 16; o; o >>= 1) v += __shfl_xor_sync(0xffffffffu, v, o);
    return v;
}

// packed f32x2 helpers (sm_100+)
__device__ __forceinline__ void fma2(ull &d, ull a, ull b) {
    asm("fma.rn.f32x2 %0, %1, %2, %0;" : "+l"(d) : "l"(a), "l"(b));
}
__device__ __forceinline__ ull f2add(ull a, ull b) {
    ull d;
    asm("add.rn.f32x2 %0, %1, %2;" : "=l"(d) : "l"(a), "l"(b));
    return d;
}
__device__ __forceinline__ ull f2mul(ull a, ull b) {
    ull d;
    asm("mul.rn.f32x2 %0, %1, %2;" : "=l"(d) : "l"(a), "l"(b));
    return d;
}
__device__ __forceinline__ float f2sum(ull u) {
    float lo, hi;
    asm("mov.b64 {%0,%1}, %2;" : "=f"(lo), "=f"(hi) : "l"(u));
    return lo + hi;
}
__device__ __forceinline__ ull packf2(float x, float y) {
    ull u;
    asm("mov.b64 %0, {%1,%2};" : "=l"(u) : "f"(x), "f"(y));
    return u;
}
__device__ __forceinline__ ull shfl_xor_ull(ull v, int m) {
    unsigned lo = (unsigned)v, hi = (unsigned)(v >> 32);
    lo = __shfl_xor_sync(0xffffffffu, lo, m);
    hi = __shfl_xor_sync(0xffffffffu, hi, m);
    return ((ull)hi << 32) | lo;
}

// ---------------- mbarrier + bulk-copy helpers ----------------
__device__ __forceinline__ void mbar_init(unsigned a, unsigned cnt) {
    asm volatile("mbarrier.init.shared.b64 [%0], %1;" :: "r"(a), "r"(cnt) : "memory");
}
__device__ __forceinline__ void mbar_expect_tx(unsigned a, unsigned bytes) {
    asm volatile("mbarrier.arrive.expect_tx.shared.b64 _, [%0], %1;"
                 :: "r"(a), "r"(bytes) : "memory");
}
__device__ __forceinline__ void bulk_g2s(unsigned dst, const void* src, unsigned bytes, unsigned mbar) {
    asm volatile("cp.async.bulk.shared::cta.global.mbarrier::complete_tx::bytes [%0], [%1], %2, [%3];"
                 :: "r"(dst), "l"(src), "r"(bytes), "r"(mbar) : "memory");
}
#define MBAR_WAIT(addr, par) do { \
    asm volatile( \
        "{\n\t.reg .pred P;\n\t" \
        "WL%=:\n\t" \
        "mbarrier.try_wait.parity.acquire.cta.shared::cta.b64 P, [%0], %1, 0x989680;\n\t" \
        "@P bra WD%=;\n\t" \
        "bra WL%=;\n\t" \
        "WD%=:\n\t}" \
        :: "r"(addr), "r"(par) : "memory"); \
} while (0)

#define GROUP_BAR(gid) \
    asm volatile("bar.sync %0, 256;" :: "r"((gid) + 1) : "memory")

// ---------------- K0: zero accumulators ----------------
__global__ void zero_kernel() {
    int i = blockIdx.x * 256 + threadIdx.x;
    if (i < BB*EE) { g_asum[i] = 0.f; g_acnt[i] = 0; }
}

// ---------------- K0a: pack weights into d-pairs ----------------
__global__ void __launch_bounds__(256) pack_kernel(
    const float* __restrict__ Wq, const float* __restrict__ Wk,
    const float* __restrict__ Wv, const float* __restrict__ Wfc)
{
    int i = blockIdx.x * 256 + threadIdx.x;    // 32768
    int j = i >> 8, col = i & 255;
    int i0 = (2*j)*256 + col, i1 = (2*j + 1)*256 + col;
    g_w2q[i] = packf2(Wq[i0],  Wq[i1]);
    g_w2k[i] = packf2(Wk[i0],  Wk[i1]);
    g_w2v[i] = packf2(Wv[i0],  Wv[i1]);
    g_w2f[i] = packf2(Wfc[i0], Wfc[i1]);
}

// ---------------- K0b: valid counts + d8 compression ----------------
__global__ void __launch_bounds__(256) countwrite_kernel(const int* __restrict__ dist) {
    int b  = blockIdx.y;
    int q0 = blockIdx.x * 8;
    int t  = threadIdx.x;
    const int* dpb = dist + (long long)b*EE*EE;
    unsigned char* d8 = g_d8 + (long long)b*EE*D8_LD;
    for (int k = t; k < EE; k += 256) {
        int cnt = 0;
        #pragma unroll
        for (int r = 0; r < 8; r++) {
            int q = q0 + r;
            if (q < EE) {
                int dv = dpb[(long long)q*EE + k];
                bool ok = (dv <= 3);
                d8[q*D8_LD + k] = ok ? (unsigned char)dv : (unsigned char)255;
                cnt += ok ? 1 : 0;
            }
        }
        atomicAdd(&g_acnt[b*EE + k], cnt);
    }
}

// ---------------- K1: layernorm + QKV projections (8 rows, d-paired f32x2) ----------------
// pair layouts: s2/n2[(dp*9 + r)*2 + par] = value at d = 2*dp+par, row r (9-stride pad
// makes fills / layernorm accesses conflict-free)
__global__ void __launch_bounds__(256) proj_kernel(
    const float* __restrict__ x,
    const float* __restrict__ lnw, const float* __restrict__ lnb,
    const float* __restrict__ rpr)
{
    __shared__ __align__(16) float ssm2[2304];   // 128 dpairs x 9 rows x 2
    __shared__ __align__(16) float nsm2[2304];
    int b  = blockIdx.y;
    int e0 = blockIdx.x * 8;
    int t  = threadIdx.x;
    const float* xb = x + b*(DD*EE);

    for (int i = t; i < 2048; i += 256) {
        int d = i >> 3, r = i & 7;
        int e = e0 + r;
        ssm2[((d >> 1)*9 + r)*2 + (d & 1)] = (e < EE) ? xb[d*EE + e] : 0.f;
    }
    __syncthreads();

    int w = t >> 5, lane = t & 31;
    {   // layernorm of row w (one row per warp)
        float s = 0.f;
        #pragma unroll
        for (int i = 0; i < 8; i++) {
            int d = lane + 32*i;
            s += ssm2[((d >> 1)*9 + w)*2 + (d & 1)];
        }
        s = warp_sum(s);
        float mu = s * (1.f/256.f);
        float vs = 0.f;
        #pragma unroll
        for (int i = 0; i < 8; i++) {
            int d = lane + 32*i;
            float dlt = ssm2[((d >> 1)*9 + w)*2 + (d & 1)] - mu;
            vs += dlt*dlt;
        }
        vs = warp_sum(vs);
        float rstd = rsqrtf(vs * (1.f/256.f) + 1e-6f);
        #pragma unroll
        for (int i = 0; i < 8; i++) {
            int d = lane + 32*i;
            int idx = ((d >> 1)*9 + w)*2 + (d & 1);
            nsm2[idx] = (ssm2[idx] - mu) * rstd * lnw[d] + lnb[d];
        }
    }
    __syncthreads();

    int j = t;
    ull aq2[8], ak2[8], av2[8];
    #pragma unroll
    for (int r = 0; r < 8; r++) { aq2[r] = 0; ak2[r] = 0; av2[r] = 0; }

    const ull* s2u = (const ull*)ssm2;
    const ull* n2u = (const ull*)nsm2;
    #pragma unroll 2
    for (int dp = 0; dp < 128; dp++) {
        ull wq2 = g_w2q[dp*256 + j];
        ull wk2 = g_w2k[dp*256 + j];
        ull wv2 = g_w2v[dp*256 + j];
        #pragma unroll
        for (int r = 0; r < 8; r++) {
            ull s2 = s2u[dp*9 + r];
            ull n2 = n2u[dp*9 + r];
            fma2(aq2[r], n2, wq2);
            fma2(ak2[r], s2, wk2);
            fma2(av2[r], s2, wv2);
        }
    }

    float aq[8], ak[8], av[8];
    #pragma unroll
    for (int r = 0; r < 8; r++) {
        aq[r] = f2sum(aq2[r]);
        ak[r] = f2sum(ak2[r]);
        av[r] = f2sum(av2[r]);
    }

    int h = j >> 5, dk = j & 31;
    int bh = b*HH + h;
    const float inv_sqrt_dk = 0.17677669529663687f;  // 1/sqrt(32)
    float qsv[8];
    #pragma unroll
    for (int r = 0; r < 8; r++) qsv[r] = aq[r] * inv_sqrt_dk;

    #pragma unroll
    for (int r = 0; r < 8; r++) {
        int e = e0 + r;
        if (e < EE) {
            g_q[(bh*EE + e)*32 + dk] = qsv[r];
            g_v[((long long)bh*1536 + e)*32 + dk] = av[r];
        }
    }

    #pragma unroll
    for (int p = 0; p < 6; p++) {
        float rv = rpr[p*32 + lane];
        #pragma unroll
        for (int r = 0; r < 8; r++) {
            float pv = warp_sum(qsv[r] * rv);
            if (lane == 0 && (e0 + r) < EE)
                g_qdr[(bh*EE + (e0 + r))*8 + p] = pv;
        }
    }

    // ---- K pair-transpose into chunk-major g_k2[bh][c][j][64] ----
    __syncthreads();                     // all ssm2/nsm2 reads done; reuse ssm2 as scratch
    float* scratch = ssm2;               // 2048 <= 2304 floats
    #pragma unroll
    for (int r = 0; r < 8; r++) scratch[t*8 + r] = ak[r];   // scratch[(h*32+dk)][r]
    __syncthreads();
    {
        int hh = t >> 5;                 // 0..7
        int jj = (t >> 1) & 15;          // 0..15 d-pair
        int ph = t & 1;                  // which half of the 4 pairs
        const float* s0 = &scratch[(hh*32 + 2*jj    )*8];
        const float* s1 = &scratch[(hh*32 + 2*jj + 1)*8];
        int pg = e0 >> 1;                // first pair (multiple of 4)
        int cc = pg >> 6, pl = pg & 63;
        long long base = (((long long)(b*HH + hh)*12 + cc)*16 + jj)*64 + pl + 2*ph;
        #pragma unroll
        for (int ps = 0; ps < 2; ps++) {
            int ee = 4*ph + 2*ps;        // local e of even k
            ulonglong2 val;
            val.x = packf2(s0[ee],   s1[ee]);
            val.y = packf2(s0[ee+1], s1[ee+1]);
            g_k2[base + ps] = val;
        }
    }
}

// ---------------- K2: attention (two independent 256-thread groups) ----------------
#define SC_LD 1512
// floats: mbar 16 + sc 16*1512 + 4 bufs (4*4096) + qsm 512 + qdr 128 + flaginv 16 + invr 16
#define SMEM_ATTN ((16 + 16*SC_LD + 4*4096 + 512 + 128 + 16 + 16)*4)
#define CHUNK_BYTES 16384u

__global__ void __launch_bounds__(512, 1) attn_kernel(float* __restrict__ out)
{
    extern __shared__ __align__(16) float sm[];
    float* sc      = sm + 16;                // 16 x 1512 (group g owns rows [8g, 8g+8))
    float* bufs    = sc + 16*SC_LD;          // 4 x 4096 floats: [g][buf]
    float* qsm     = bufs + 4*4096;          // 16 x 32 scaled q
    float* qdr     = qsm + 512;              // 16 x 8 bias table
    float* flaginv = qdr + 128;              // 16: inv (or 0 if fullmask)
    float* invr    = flaginv + 16;           // 16: inv always

    int qt = blockIdx.x, h = blockIdx.y, b = blockIdx.z;
    int q0 = qt * 16;
    int t  = threadIdx.x;
    int g  = t >> 8;          // group 0/1
    int gt = t & 255;         // thread within group
    int w8 = gt >> 5;         // warp within group
    int lane = gt & 31;
    int bh = b*HH + h;

    // per-group views
    float* scg      = sc + g*8*SC_LD;
    float* buf0f    = bufs + g*2*4096;
    float* buf1f    = buf0f + 4096;
    float* qsmg     = qsm + g*256;
    float* qdrg     = qdr + g*64;
    float* flaginvg = flaginv + g*8;
    float* invrg    = invr + g*8;

    unsigned smb = (unsigned)__cvta_generic_to_shared(sm) + g*32;
    unsigned mbK0 = smb, mbK1 = smb + 8, mbV0 = smb + 16, mbV1 = smb + 24;
    unsigned bsm0 = (unsigned)__cvta_generic_to_shared(buf0f);
    unsigned bsm1 = (unsigned)__cvta_generic_to_shared(buf1f);

    const ulonglong2* k2base = g_k2 + (long long)bh*12*1024;
    const float* vbase = g_v + (long long)bh*1536*32;
    const unsigned char* d8b = g_d8 + (long long)b*EE*D8_LD;

    // prologue: q rows for this group (8 rows x 32), bias rows, mbar init, first K copies
    {
        int qg = q0 + g*8 + (gt >> 5);
        qsmg[gt] = (qg < EE) ? g_q[(bh*EE + qg)*32 + (gt & 31)] : 0.f;
    }
    if (gt < 64) {
        int qg = q0 + g*8 + (gt >> 3);
        qdrg[gt] = (qg < EE) ? g_qdr[(bh*EE + qg)*8 + (gt & 7)] : 0.f;
    }
    if (gt == 0) {
        mbar_init(mbK0, 1); mbar_init(mbK1, 1);
        mbar_init(mbV0, 1); mbar_init(mbV1, 1);
        mbar_expect_tx(mbK0, CHUNK_BYTES);
        bulk_g2s(bsm0, k2base, CHUNK_BYTES, mbK0);
        mbar_expect_tx(mbK1, CHUNK_BYTES);
        bulk_g2s(bsm1, k2base + 1024, CHUNK_BYTES, mbK1);
    }
    GROUP_BAR(g);

    // ================= score phase =================
    // group warp w8 owns pairs [w8*8, w8*8+8); lane: qq = (gt>>3)&3, kl = gt&7
    int qq = (gt >> 3) & 3;
    int p0i = w8*8 + (gt & 7);
    int qg0 = q0 + g*8 + qq, qg1 = qg0 + 4;

    // Q rows into registers (broadcast LDS, once)
    ull qr0[16], qr1[16];
    {
        const ull* a = (const ull*)(qsmg + qq*32);
        const ull* bq = (const ull*)(qsmg + (qq + 4)*32);
        #pragma unroll
        for (int jj = 0; jj < 16; jj++) { qr0[jj] = a[jj]; qr1[jj] = bq[jj]; }
    }

    // d8 prologue for chunk 0
    uchar2 dA, dB;
    {
        int kgA = 2*p0i;
        dA = (qg0 < EE) ? *(const uchar2*)(d8b + (long long)qg0*D8_LD + kgA) : make_uchar2(255, 255);
        dB = (qg1 < EE) ? *(const uchar2*)(d8b + (long long)qg1*D8_LD + kgA) : make_uchar2(255, 255);
    }

    for (int c = 0; c < 12; c++) {
        int kc = c * 128;
        // prefetch d8 for chunk c+1 (overlaps mbar wait + compute)
        uchar2 eA = make_uchar2(255, 255), eB = make_uchar2(255, 255);
        if (c < 11) {
            int kg2 = kc + 128 + 2*p0i;
            if (kg2 < EE) {
                if (qg0 < EE) eA = *(const uchar2*)(d8b + (long long)qg0*D8_LD + kg2);
                if (qg1 < EE) eB = *(const uchar2*)(d8b + (long long)qg1*D8_LD + kg2);
            }
        }

        MBAR_WAIT((c & 1) ? mbK1 : mbK0, (c >> 1) & 1);

        const ulonglong2* bp = (const ulonglong2*)((c & 1) ? buf1f : buf0f);
        const ulonglong2* prow = bp + p0i;
        ull a00 = 0, a01 = 0, a10 = 0, a11 = 0;
        #pragma unroll
        for (int jj = 0; jj < 16; jj++) {
            ulonglong2 kv = prow[jj*64];
            fma2(a00, qr0[jj], kv.x); fma2(a01, qr0[jj], kv.y);
            fma2(a10, qr1[jj], kv.x); fma2(a11, qr1[jj], kv.y);
        }

        // epilogue: bias + mask + paired store
        int kgA = kc + 2*p0i;
        if (kgA < EE) {
            float sa = -1e9f, sb = -1e9f;
            if (dA.x <= 3) sa = f2sum(a00) + qdrg[qq*8 + dA.x];
            if (dA.y <= 3) sb = f2sum(a01) + qdrg[qq*8 + dA.y];
            *(ull*)&scg[qq*SC_LD + kgA] = packf2(sa, sb);
            sa = -1e9f; sb = -1e9f;
            if (dB.x <= 3) sa = f2sum(a10) + qdrg[(qq + 4)*8 + dB.x];
            if (dB.y <= 3) sb = f2sum(a11) + qdrg[(qq + 4)*8 + dB.y];
            *(ull*)&scg[(qq + 4)*SC_LD + kgA] = packf2(sa, sb);
        }
        GROUP_BAR(g);   // all reads of buf[c&1] done, sc stores visible
        if (gt == 0 && c < 10) {
            unsigned mb = (c & 1) ? mbK1 : mbK0;
            mbar_expect_tx(mb, CHUNK_BYTES);
            bulk_g2s((c & 1) ? bsm1 : bsm0, k2base + (c + 2)*1024, CHUNK_BYTES, mb);
        }
        dA = eA; dB = eB;
    }

    // issue V chunks 0,1 (overlap with softmax)
    if (gt == 0) {
        mbar_expect_tx(mbV0, CHUNK_BYTES);
        bulk_g2s(bsm0, vbase, CHUNK_BYTES, mbV0);
        mbar_expect_tx(mbV1, CHUNK_BYTES);
        bulk_g2s(bsm1, vbase + 128*32, CHUNK_BYTES, mbV1);
    }

    // ===== softmax, 2-pass (no max subtraction; masked -1e9 underflows to 0) =====
    {
        int rr = w8;                  // one row per group warp
        int qg = q0 + g*8 + rr;
        if (qg < EE) {
            float* row = scg + rr*SC_LD;
            float sum = 0.f;
            for (int k = lane*4; k < EE; k += 128) {
                float4 v = *(float4*)&row[k];
                v.x = __expf(v.x); v.y = __expf(v.y);
                v.z = __expf(v.z); v.w = __expf(v.w);
                *(float4*)&row[k] = v;
                sum += (v.x + v.y) + (v.z + v.w);
            }
            sum = warp_sum(sum);
            bool fullmask = (sum == 0.f);
            if (fullmask) {   // reference: softmax of all -1e9 -> uniform
                for (int k = lane*4; k < EE; k += 128)
                    *(float4*)&row[k] = make_float4(1.f, 1.f, 1.f, 1.f);
                sum = (float)EE;
            }
            float inv = 1.f / sum;
            if (lane == 0) {
                invrg[rr] = inv;
                flaginvg[rr] = fullmask ? 0.f : inv;
            }
            long long obase = (long long)O_ATTN + (long long)(bh*EE + qg)*EE;
            for (int k = lane*4; k < EE; k += 128) {
                float4 v = *(const float4*)&row[k];
                v.x *= inv; v.y *= inv; v.z *= inv; v.w *= inv;
                *(float4*)&out[obase + k] = v;
            }
        } else {
            if (lane == 0) { invrg[rr] = 0.f; flaginvg[rr] = 0.f; }
        }
    }
    GROUP_BAR(g);

    // column sums over this group's 8 rows (unnormalized exp * flaginv)
    for (int k = gt; k < EE; k += 256) {
        float s = 0.f;
        #pragma unroll
        for (int r = 0; r < 8; r++) s += scg[r*SC_LD + k] * flaginvg[r];
        atomicAdd(&g_asum[b*EE + k], s);
    }

    // ================= AV =================
    // thread = (ks = gt>>3: 32 k-slices of 4, dp = gt&7: float4 of d)
    // owns ALL 8 group rows; accumulates across all 12 chunks in registers.
    int ks = gt >> 3;
    int dp = gt & 7;
    ull accL[8], accH[8];
    #pragma unroll
    for (int r = 0; r < 8; r++) { accL[r] = 0; accH[r] = 0; }

    for (int c = 0; c < 12; c++) {
        int kc = c * 128;
        MBAR_WAIT((c & 1) ? mbV1 : mbV0, (c >> 1) & 1);
        const float4* bp4 = (const float4*)((c & 1) ? buf1f : buf0f);

        int kg0 = kc + ks*4;
        if (kg0 < EE) {
            float4 a[8];
            #pragma unroll
            for (int r = 0; r < 8; r++)
                a[r] = *(const float4*)&scg[r*SC_LD + kg0];
            #pragma unroll
            for (int kk = 0; kk < 4; kk++) {
                float4 vv = bp4[(ks*4 + kk)*8 + dp];
                ull v0 = packf2(vv.x, vv.y), v1 = packf2(vv.z, vv.w);
                #pragma unroll
                for (int r = 0; r < 8; r++) {
                    float f = (kk==0) ? a[r].x : (kk==1) ? a[r].y : (kk==2) ? a[r].z : a[r].w;
                    ull s = packf2(f, f);
                    fma2(accL[r], s, v0);
                    fma2(accH[r], s, v1);
                }
            }
        }
        GROUP_BAR(g);   // all reads of buf[c&1] done
        if (gt == 0 && c < 10) {
            unsigned mb = (c & 1) ? mbV1 : mbV0;
            mbar_expect_tx(mb, CHUNK_BYTES);
            bulk_g2s((c & 1) ? bsm1 : bsm0, vbase + (long long)(c + 2)*128*32, CHUNK_BYTES, mb);
        }
    }

    // intra-warp reduction over the 4 k-slices in this warp (lane bits 3,4)
    #pragma unroll
    for (int r = 0; r < 8; r++) {
        accL[r] = f2add(accL[r], shfl_xor_ull(accL[r], 8));
        accL[r] = f2add(accL[r], shfl_xor_ull(accL[r], 16));
        accH[r] = f2add(accH[r], shfl_xor_ull(accH[r], 8));
        accH[r] = f2add(accH[r], shfl_xor_ull(accH[r], 16));
    }

    // cross-warp k-reduction via smem partials (group's sc region is free now)
    {
        ulonglong2* part = (ulonglong2*)scg;   // [w8][row][dp] : 8*8*8 ull2 = 8 KB
        if (lane < 8) {   // dp == lane for these lanes
            #pragma unroll
            for (int r = 0; r < 8; r++) {
                ulonglong2 v; v.x = accL[r]; v.y = accH[r];
                part[(w8*8 + r)*8 + dp] = v;
            }
        }
    }
    GROUP_BAR(g);
    if (gt < 64) {
        const ulonglong2* part = (const ulonglong2*)scg;
        int row = gt >> 3, dpp = gt & 7;
        ull sA = 0, sB = 0;
        #pragma unroll
        for (int ww = 0; ww < 8; ww++) {
            ulonglong2 v = part[(ww*8 + row)*8 + dpp];
            sA = f2add(sA, v.x);
            sB = f2add(sB, v.y);
        }
        int qg = q0 + g*8 + row;
        if (qg < EE) {
            float iv = invrg[row];
            ull ivp = packf2(iv, iv);
            ulonglong2 o;
            o.x = f2mul(sA, ivp);
            o.y = f2mul(sB, ivp);
            *(ulonglong2*)&g_o[(b*EE + qg)*DD + h*32 + 4*dpp] = o;
        }
    }
}

// ---------------- K3: FC + residual + transpose-out (8 rows, d-paired f32x2) ----------------
__global__ void __launch_bounds__(256) fc_kernel(
    const float* __restrict__ x, float* __restrict__ out)
{
    __shared__ __align__(16) float osm2[2304];   // 128 dpairs x 9 rows x 2
    int b  = blockIdx.y;
    int e0 = blockIdx.x * 8;
    int t  = threadIdx.x;

    for (int i = t; i < 2048; i += 256) {
        int r = i >> 8, d = i & 255;
        int e = e0 + r;
        osm2[((d >> 1)*9 + r)*2 + (d & 1)] = (e < EE) ? g_o[(b*EE + e)*DD + d] : 0.f;
    }
    __syncthreads();

    int j = t;
    ull acc2[8];
    #pragma unroll
    for (int r = 0; r < 8; r++) acc2[r] = 0;

    const ull* o2u = (const ull*)osm2;
    #pragma unroll 2
    for (int dp = 0; dp < 128; dp++) {
        ull w2 = g_w2f[dp*256 + j];
        #pragma unroll
        for (int r = 0; r < 8; r++)
            fma2(acc2[r], o2u[dp*9 + r], w2);
    }

    const float* xb = x + b*DD*EE + j*EE;
    float acc[8];
    #pragma unroll
    for (int r = 0; r < 8; r++) {
        int e = e0 + r;
        acc[r] = f2sum(acc2[r]) + ((e < EE) ? xb[e] : 0.f);
    }
    float* ob = out + b*DD*EE + j*EE + e0;
    if (e0 + 8 <= EE) {
        *(float4*)ob       = make_float4(acc[0], acc[1], acc[2], acc[3]);
        *(float4*)(ob + 4) = make_float4(acc[4], acc[5], acc[6], acc[7]);
    } else {
        for (int r = 0; r < 8; r++)
            if (e0 + r < EE) ob[r] = acc[r];
    }
}

// ---------------- K4: attn_per_edge ----------------
__global__ void finalize_kernel(float* __restrict__ out) {
    int i = blockIdx.x * 256 + threadIdx.x;
    if (i < BB*EE) {
        out[O_APE + i] = g_asum[i] / (float)g_acnt[i];
    }
}

// ---------------- launch ----------------
extern "C" void kernel_launch(void* const* d_in, const int* in_sizes, int n_in,
                              void* d_out, int out_size)
{
    const float* x    = (const float*)d_in[0];
    const int*   dist = (const int*)  d_in[1];
    const float* Wq   = (const float*)d_in[2];
    const float* Wk   = (const float*)d_in[3];
    const float* Wv   = (const float*)d_in[4];
    const float* Wfc  = (const float*)d_in[5];
    const float* lnw  = (const float*)d_in[6];
    const float* lnb  = (const float*)d_in[7];
    const float* rpr  = (const float*)d_in[8];
    float* out = (float*)d_out;

    cudaFuncSetAttribute(attn_kernel,
        cudaFuncAttributeMaxDynamicSharedMemorySize, SMEM_ATTN);

    zero_kernel<<<24, 256>>>();
    pack_kernel<<<128, 256>>>(Wq, Wk, Wv, Wfc);

    dim3 gc(188, BB);
    countwrite_kernel<<<gc, 256>>>(dist);

    dim3 g1(188, BB);
    proj_kernel<<<g1, 256>>>(x, lnw, lnb, rpr);

    dim3 g2(94, HH, BB);
    attn_kernel<<<g2, 512, SMEM_ATTN>>>(out);

    dim3 g3(188, BB);
    fc_kernel<<<g3, 256>>>(x, out);

    finalize_kernel<<<24, 256>>>(out);
}